// round 14
// baseline (speedup 1.0000x reference)
#include <cuda_runtime.h>
#include <cuda_bf16.h>
#include <math.h>
#include <stdint.h>

// ---------------- problem constants ----------------
#define LSEQ   1024
#define BATCH  8
#define CDIM   256
#define DINNER 512
#define DSTATE 16
#define NROWS  (BATCH*LSEQ)   // 8192

typedef __nv_bfloat16 bf16;
typedef __nv_bfloat162 bf162;

// ---------------- scratch (static, no allocs) ----------------
__device__ __align__(256) bf16     g_xnh  [(size_t)NROWS*CDIM];
__device__ __align__(256) bf16     g_uh   [(size_t)NROWS*DINNER];
__device__ __align__(256) bf16     g_gzh  [(size_t)NROWS*DINNER];   // silu(z), [row][d]
__device__ __align__(256) bf16     g_u2h  [(size_t)NROWS*DINNER];
__device__ __align__(256) uint32_t g_du   [(size_t)NROWS*DINNER];   // (dt,u2) pack, [row][d]
__device__ __align__(256) float2   g_bc   [(size_t)NROWS*DSTATE];   // [row][s]
__device__ __align__(256) bf16     g_ygh  [(size_t)NROWS*DINNER];   // [row][d]
// weights, bf16, K-major [N][K]
__device__ __align__(256) bf16     g_WinT  [(size_t)1024*CDIM];
__device__ __align__(256) bf16     g_w2T   [(size_t)640*DINNER];    // [0:512)=wcomb, [512:544)=Wbc, rest 0
__device__ __align__(256) bf16     g_WoutT [(size_t)CDIM*DINNER];

// ---------------- small helpers ----------------
__device__ __forceinline__ float siluf(float v) { return v / (1.f + __expf(-v)); }
__device__ __forceinline__ float softplusf(float v) {
    return (v > 20.f) ? v : log1pf(__expf(v));
}
__device__ __forceinline__ uint32_t pbf2(float lo, float hi) {
    uint32_t r;
    asm("cvt.rn.bf16x2.f32 %0, %1, %2;" : "=r"(r) : "f"(hi), "f"(lo));
    return r;
}
__device__ __forceinline__ uint32_t smem_u32(const void* p) {
    return (uint32_t)__cvta_generic_to_shared(p);
}
__device__ __forceinline__ void cp16(uint32_t sm, const void* gm) {
    asm volatile("cp.async.cg.shared.global [%0], [%1], 16;\n" :: "r"(sm), "l"(gm));
}
__device__ __forceinline__ void cp16ca(uint32_t sm, const void* gm) {
    asm volatile("cp.async.ca.shared.global [%0], [%1], 16;\n" :: "r"(sm), "l"(gm));
}
__device__ __forceinline__ void ldsm4(uint32_t* r, uint32_t addr) {
    asm volatile("ldmatrix.sync.aligned.m8n8.x4.shared.b16 {%0,%1,%2,%3}, [%4];"
        : "=r"(r[0]), "=r"(r[1]), "=r"(r[2]), "=r"(r[3]) : "r"(addr));
}
__device__ __forceinline__ void mma16(float* c, const uint32_t* a, const uint32_t* b) {
    asm volatile(
        "mma.sync.aligned.m16n8k16.row.col.f32.bf16.bf16.f32 "
        "{%0,%1,%2,%3}, {%4,%5,%6,%7}, {%8,%9}, {%0,%1,%2,%3};\n"
        : "+f"(c[0]), "+f"(c[1]), "+f"(c[2]), "+f"(c[3])
        : "r"(a[0]), "r"(a[1]), "r"(a[2]), "r"(a[3]), "r"(b[0]), "r"(b[1]));
}

// ---------------- merged prep kernel: ln + prepA + prepBW ----------
__device__ __forceinline__ void tconv_body(char* smc, const float* src, bf16* dst,
                                           int K, int ldsrc, int coloff,
                                           int n0, int k0, int t) {
    float (*sm)[33] = (float(*)[33])smc;
    #pragma unroll
    for (int p = 0; p < 4; p++) {
        int ki = p*8 + (t >> 5);
        sm[ki][t & 31] = src[(size_t)(k0+ki)*ldsrc + coloff + n0 + (t & 31)];
    }
    __syncthreads();
    #pragma unroll
    for (int p = 0; p < 4; p++) {
        int ni = p*8 + (t >> 5);
        dst[(size_t)(n0+ni)*K + k0 + (t & 31)] = __float2bfloat16(sm[t & 31][ni]);
    }
}

__global__ __launch_bounds__(256) void prep_kernel(
    const float* __restrict__ x, const float* __restrict__ gamma,
    const float* __restrict__ beta, const float* __restrict__ W_in,
    const float* __restrict__ W_out, const float* __restrict__ W_xproj,
    const float* __restrict__ W_dt)
{
    __shared__ __align__(16) char smc[35840];
    const int bid = blockIdx.x, t = threadIdx.x;
    if (bid < 256) {
        float* sm   = (float*)smc;
        float* s_mu = sm + 32*257;
        float* s_rs = s_mu + 32;
        const int b  = bid >> 5;
        const int l0 = (bid & 31) * 32;
        #pragma unroll
        for (int j = 0; j < 32; j++) {
            int e = j*256 + t;
            sm[(e & 31)*257 + (e >> 5)] =
                x[((size_t)(b*CDIM + (e >> 5)))*LSEQ + l0 + (e & 31)];
        }
        __syncthreads();
        const int w = t >> 5, lane = t & 31;
        #pragma unroll
        for (int q = 0; q < 4; q++) {
            int li = w*4 + q;
            float s = 0.f, s2 = 0.f;
            #pragma unroll
            for (int j = 0; j < 8; j++) {
                float v = sm[li*257 + lane + j*32];
                s += v; s2 = fmaf(v, v, s2);
            }
            #pragma unroll
            for (int o = 16; o; o >>= 1) {
                s  += __shfl_xor_sync(0xffffffffu, s,  o);
                s2 += __shfl_xor_sync(0xffffffffu, s2, o);
            }
            if (lane == 0) {
                float mu = s * (1.f/CDIM);
                s_mu[li] = mu;
                s_rs[li] = rsqrtf(s2 * (1.f/CDIM) - mu*mu + 1e-5f);
            }
        }
        __syncthreads();
        const float g = gamma[t], be = beta[t];
        #pragma unroll
        for (int li = 0; li < 32; li++) {
            float v = (sm[li*257 + t] - s_mu[li]) * s_rs[li];
            g_xnh[((size_t)(b*LSEQ + l0 + li))*CDIM + t] =
                __float2bfloat16(fmaf(v, g, be));
        }
    } else if (bid < 512) {
        int i = bid - 256;
        tconv_body(smc, W_in, g_WinT, CDIM, 1024, 0, (i & 31)*32, (i >> 5)*32, t);
    } else if (bid < 640) {
        int i = bid - 512;
        tconv_body(smc, W_out, g_WoutT, DINNER, 256, 0, (i & 7)*32, (i >> 3)*32, t);
    } else if (bid < 656) {
        tconv_body(smc, W_xproj, g_w2T + (size_t)512*DINNER, DINNER, 48, 16, 0,
                   (bid - 640)*32, t);
    } else {
        float (*s_wx)[17] = (float(*)[17])smc;
        float (*s_wd)[8]  = (float(*)[8])(smc + 512*17*4);
        const int wb = bid - 656;
        const int n8 = wb*8;
        #pragma unroll
        for (int i = 0; i < 32; i++) {
            int idx = t + i*256;
            s_wx[idx >> 4][idx & 15] = W_xproj[(idx >> 4)*48 + (idx & 15)];
        }
        if (t < 128) s_wd[t >> 3][t & 7] = W_dt[(t >> 3)*DINNER + n8 + (t & 7)];
        __syncthreads();
        const int w = t >> 5, lane = t & 31;
        const int n = n8 + w;
        for (int k = lane; k < DINNER; k += 32) {
            float a = 0.f;
            #pragma unroll
            for (int j = 0; j < 16; j++) a = fmaf(s_wx[k][j], s_wd[j][w], a);
            g_w2T[(size_t)n*DINNER + k] = __float2bfloat16(a);
        }
        uint32_t* zp = (uint32_t*)(g_w2T + (size_t)544*DINNER);
        int i0 = wb*384 + t;
        zp[i0] = 0;
        if (t < 128) zp[i0 + 256] = 0;
    }
}

// ---------------- bf16 mma.sync GEMM, 4-stage cp.async, batched LDSM ----------------
// MODE 1: col<512 -> u bf16 (g_uh); col>=512 -> silu -> g_gzh
// MODE 4: combined G2+G3: n0<512 -> (dt,u2) pack -> g_du; n0==512 -> bc pack (wn==0;
//         warps wn!=0 in the pad block skip all fragment/mma work — outputs unused)
// MODE 5: out-fused: smem-transpose fp32 tile, out[b][c][l] = v + x  (Cf=out, e0=x)
template<int MODE>
__global__ __launch_bounds__(256, 2) void gemm_mma(
    const bf16* __restrict__ A, const bf16* __restrict__ Bt,
    float* __restrict__ Cf, const float* __restrict__ e0,
    int K)
{
    constexpr int BM = 128, BN = 128, WM = 64, WN = 32;
    constexpr int BK = 32, ST = 4;
    constexpr int LDA = BK + 8;
    extern __shared__ bf16 sm[];
    bf16* As = sm;
    bf16* Bs = sm + (size_t)ST*BM*LDA;
    const int tid = threadIdx.x, wid = tid >> 5, lane = tid & 31;
    const int g = lane >> 2, q = lane & 3;
    const int wm = wid >> 2, wn = wid & 3;
    const int m0 = blockIdx.y * BM, n0 = blockIdx.x * BN;
    constexpr int MF = WM / 16, NF = WN / 8;
    float acc[MF][NF][4] = {};
    // pad-block dead warps (MODE4, n0>=512, wn!=0): outputs never stored
    const bool active = !(MODE == 4 && n0 >= DINNER && wn != 0);

    auto load_stage = [&](int s, int kt) {
        const int k0 = kt * BK;
        #pragma unroll
        for (int i = 0; i < BM*4/256; i++) {
            int idx = tid + i*256;
            int r = idx >> 2, c = idx & 3;
            cp16(smem_u32(&As[(s*BM + r)*LDA + c*8]), &A[(size_t)(m0+r)*K + k0 + c*8]);
        }
        #pragma unroll
        for (int i = 0; i < BN*4/256; i++) {
            int idx = tid + i*256;
            int r = idx >> 2, c = idx & 3;
            cp16ca(smem_u32(&Bs[(s*BN + r)*LDA + c*8]), &Bt[(size_t)(n0+r)*K + k0 + c*8]);
        }
        asm volatile("cp.async.commit_group;\n");
    };
    auto compute = [&](int s) {
        uint32_t aB = smem_u32(As)
            + (uint32_t)(((s*BM + wm*WM + (lane & 15))*LDA + ((lane >> 4) << 3)) * 2);
        uint32_t bB = smem_u32(Bs)
            + (uint32_t)(((s*BN + wn*WN + ((lane >> 4) << 3) + (lane & 7))*LDA
                          + (((lane >> 3) & 1) << 3)) * 2);
        uint32_t af[2][MF][4], bfr[2][NF][2];
        #pragma unroll
        for (int h = 0; h < 2; h++) {
            #pragma unroll
            for (int i = 0; i < MF; i++)
                ldsm4(af[h][i], aB + (uint32_t)((i*16*LDA + h*16) * 2));
            #pragma unroll
            for (int jj = 0; jj < NF/2; jj++) {
                uint32_t tr[4];
                ldsm4(tr, bB + (uint32_t)((jj*16*LDA + h*16) * 2));
                bfr[h][2*jj][0] = tr[0]; bfr[h][2*jj][1] = tr[1];
                bfr[h][2*jj+1][0] = tr[2]; bfr[h][2*jj+1][1] = tr[3];
            }
        }
        #pragma unroll
        for (int h = 0; h < 2; h++)
            #pragma unroll
            for (int i = 0; i < MF; i++)
                #pragma unroll
                for (int j = 0; j < NF; j++)
                    mma16(acc[i][j], af[h][i], bfr[h][j]);
    };

    const int nk = K / BK;
    load_stage(0, 0);
    load_stage(1, 1);
    load_stage(2, 2);
    #pragma unroll 1
    for (int kt = 0; kt < nk; kt++) {
        asm volatile("cp.async.wait_group 2;\n");
        __syncthreads();
        int nx = kt + 3;
        if (nx < nk) load_stage(nx % ST, nx);
        else asm volatile("cp.async.commit_group;\n");
        if (active) compute(kt % ST);
    }

    // ----- epilogues -----
    if (MODE == 5) {
        __syncthreads();
        float* smt = (float*)sm;   // 128 x 133 fp32
        #pragma unroll
        for (int i = 0; i < MF; i++) {
            int r = wm*WM + i*16 + g;
            #pragma unroll
            for (int j = 0; j < NF; j++) {
                int c = wn*WN + j*8 + 2*q;
                smt[(size_t)r*133 + c]       = acc[i][j][0];
                smt[(size_t)r*133 + c + 1]   = acc[i][j][1];
                smt[(size_t)(r+8)*133 + c]   = acc[i][j][2];
                smt[(size_t)(r+8)*133 + c+1] = acc[i][j][3];
            }
        }
        __syncthreads();
        const int b = m0 >> 10, l0 = m0 & 1023;
        #pragma unroll 4
        for (int i = 0; i < 64; i++) {
            int idx = tid + i*256;
            int c = idx >> 7, l = idx & 127;
            size_t oi = ((size_t)(b*CDIM + n0 + c))*LSEQ + l0 + l;
            Cf[oi] = smt[(size_t)l*133 + c] + e0[oi];
        }
        return;
    }
    #pragma unroll
    for (int i = 0; i < MF; i++) {
        int row = m0 + wm*WM + i*16 + g;
        if (MODE == 1) {
            #pragma unroll
            for (int j = 0; j < NF; j++) {
                int col = n0 + wn*WN + j*8 + 2*q;
                float v0 = acc[i][j][0], v1 = acc[i][j][1];
                float v2 = acc[i][j][2], v3 = acc[i][j][3];
                if (col < DINNER) {
                    *(uint32_t*)&g_uh[(size_t)(row  )*DINNER + col] = pbf2(v0, v1);
                    *(uint32_t*)&g_uh[(size_t)(row+8)*DINNER + col] = pbf2(v2, v3);
                } else {
                    int cz = col - DINNER;
                    *(uint32_t*)&g_gzh[(size_t)(row  )*DINNER + cz] =
                        pbf2(siluf(v0), siluf(v1));
                    *(uint32_t*)&g_gzh[(size_t)(row+8)*DINNER + cz] =
                        pbf2(siluf(v2), siluf(v3));
                }
            }
        } else if (MODE == 4) {
            if (n0 < DINNER) {
                #pragma unroll
                for (int j = 0; j < NF; j++) {
                    int col = n0 + wn*WN + j*8 + 2*q;
                    float v0 = acc[i][j][0], v1 = acc[i][j][1];
                    float v2 = acc[i][j][2], v3 = acc[i][j][3];
                    float b0 = e0[col], b1 = e0[col+1];
                    uint32_t ua = *(const uint32_t*)&g_u2h[(size_t)(row  )*DINNER + col];
                    uint32_t ub = *(const uint32_t*)&g_u2h[(size_t)(row+8)*DINNER + col];
                    uint32_t d0 = (uint32_t)__bfloat16_as_ushort(__float2bfloat16(softplusf(v0 + b0)));
                    uint32_t d1 = (uint32_t)__bfloat16_as_ushort(__float2bfloat16(softplusf(v1 + b1)));
                    uint32_t d2 = (uint32_t)__bfloat16_as_ushort(__float2bfloat16(softplusf(v2 + b0)));
                    uint32_t d3 = (uint32_t)__bfloat16_as_ushort(__float2bfloat16(softplusf(v3 + b1)));
                    uint2 wa = make_uint2(d0 | ((ua & 0xFFFFu) << 16), d1 | (ua & 0xFFFF0000u));
                    uint2 wb = make_uint2(d2 | ((ub & 0xFFFFu) << 16), d3 | (ub & 0xFFFF0000u));
                    *(uint2*)&g_du[(size_t)(row  )*DINNER + col] = wa;
                    *(uint2*)&g_du[(size_t)(row+8)*DINNER + col] = wb;
                }
            } else if (wn == 0) {
                #pragma unroll
                for (int j = 0; j < 2; j++) {
                    int s = j*8 + 2*q;
                    float4 lo = make_float4(acc[i][j][0], acc[i][j+2][0],
                                            acc[i][j][1], acc[i][j+2][1]);
                    float4 hi = make_float4(acc[i][j][2], acc[i][j+2][2],
                                            acc[i][j][3], acc[i][j+2][3]);
                    *(float4*)&g_bc[(size_t)(row  )*DSTATE + s] = lo;
                    *(float4*)&g_bc[(size_t)(row+8)*DSTATE + s] = hi;
                }
            }
        }
    }
}

// ---------------- depthwise causal conv (D_CONV=4) + SiLU, bf162 ----------------
__global__ __launch_bounds__(256) void conv_silu_kernel(const float* __restrict__ cw,
                                                        const float* __restrict__ cb) {
    int gid = blockIdx.x*256 + threadIdx.x;
    int d2  = gid & 255;
    int row = gid >> 8;
    int l   = row & (LSEQ-1);
    int d   = d2 * 2;
    float a0 = cb[d], a1 = cb[d+1];
    const uint32_t* up = (const uint32_t*)g_uh;
    #pragma unroll
    for (int k = 0; k < 4; k++) {
        int ll = l - 3 + k;
        if (ll >= 0) {
            uint32_t w = up[(size_t)(row - 3 + k)*256 + d2];
            bf162 p = *(bf162*)&w;
            a0 = fmaf(__bfloat162float(p.x), cw[d*4 + k],     a0);
            a1 = fmaf(__bfloat162float(p.y), cw[(d+1)*4 + k], a1);
        }
    }
    ((uint32_t*)g_u2h)[gid] = pbf2(siluf(a0), siluf(a1));
}

// ---------------- selective scan v5 (verified R12) ----------------
__global__ __launch_bounds__(256) void scan_kernel(const float* __restrict__ A_log,
                                                   const float* __restrict__ D_skip) {
    __shared__ uint32_t       s_du[2][16][16];
    __shared__ float2         s_bc[2][16][16];
    __shared__ unsigned short s_gz[2][16][16];
    __shared__ unsigned short s_yg[2][16][16];
    __shared__ float          s_p [8][2][16][17];
    const int b    = blockIdx.x >> 5;
    const int dblk = (blockIdx.x & 31) * 16;
    const int tid  = threadIdx.x;
    const int widx = tid >> 5, lane = tid & 31;
    const int half = lane >> 4, s = lane & 15;
    const int ch   = 2*widx + half;
    const int d    = dblk + ch;
    const float Aval = -__expf(A_log[d*DSTATE + s]);
    const float Dd   = D_skip[d];
    const size_t rb  = (size_t)b * LSEQ;
    const int li = tid >> 4, dd = tid & 15;
    const uint32_t*       duG = g_du;
    const unsigned short* gzG = (const unsigned short*)g_gzh;
    unsigned short*       ygG = (unsigned short*)g_ygh;
    float* pbase = &s_p[widx][half][0][0];

    uint32_t r_du; unsigned short r_gz; float2 r_bc;
    auto ldchunk = [&](int c0) {
        size_t rw = (rb + c0 + li);
        r_du = duG[rw*DINNER + dblk + dd];
        r_gz = gzG[rw*DINNER + dblk + dd];
        r_bc = g_bc[rw*DSTATE + dd];
    };
    float h = 0.f;
    ldchunk(0);
    #pragma unroll 1
    for (int k = 0; k < 64; k++) {
        const int cb = k & 1;
        s_du[cb][li][dd] = r_du;
        s_gz[cb][li][dd] = r_gz;
        s_bc[cb][li][dd] = r_bc;
        __syncthreads();
        if (k > 0)
            ygG[(rb + (k-1)*16 + li)*DINNER + dblk + dd] = s_yg[cb ^ 1][li][dd];
        if (k < 63) ldchunk((k+1)*16);
        float p[16];
        #pragma unroll
        for (int j = 0; j < 16; j++) {
            uint32_t w = s_du[cb][j][ch];
            bf162 pk = *(bf162*)&w;
            float dt = __bfloat162float(pk.x);
            float u2 = __bfloat162float(pk.y);
            float2 bcv = s_bc[cb][j][s];
            float dA = __expf(dt * Aval);
            h = fmaf(dA, h, dt * u2 * bcv.x);
            p[j] = h * bcv.y;
        }
        #pragma unroll
        for (int j = 0; j < 16; j++) pbase[s*17 + j] = p[j];
        __syncwarp();
        float t[16];
        #pragma unroll
        for (int j2 = 0; j2 < 16; j2++) t[j2] = pbase[j2*17 + s];
        #pragma unroll
        for (int st = 1; st < 16; st <<= 1)
            #pragma unroll
            for (int j2 = 0; j2 < 16; j2 += 2*st) t[j2] += t[j2 + st];
        {
            uint32_t w = s_du[cb][s][ch];
            bf162 pk = *(bf162*)&w;
            float u2 = __bfloat162float(pk.y);
            float yv = t[0] + u2 * Dd;
            float gzf = __bfloat162float(__ushort_as_bfloat16(s_gz[cb][s][ch]));
            s_yg[cb][s][ch] = __bfloat16_as_ushort(__float2bfloat16(yv * gzf));
        }
    }
    __syncthreads();
    ygG[(rb + 63*16 + li)*DINNER + dblk + dd] = s_yg[1][li][dd];
}

// ---------------- host launch ----------------
extern "C" void kernel_launch(void* const* d_in, const int* in_sizes, int n_in,
                              void* d_out, int out_size) {
    const float* x       = (const float*)d_in[0];
    const float* ln_g    = (const float*)d_in[1];
    const float* ln_b    = (const float*)d_in[2];
    const float* W_in    = (const float*)d_in[3];
    const float* conv_w  = (const float*)d_in[4];
    const float* conv_b  = (const float*)d_in[5];
    const float* W_xproj = (const float*)d_in[6];
    const float* W_dt    = (const float*)d_in[7];
    const float* b_dt    = (const float*)d_in[8];
    const float* A_log   = (const float*)d_in[9];
    const float* D_skip  = (const float*)d_in[10];
    const float* W_out   = (const float*)d_in[11];
    float* out = (float*)d_out;

    bf16 *p_xnh, *p_u2h, *p_ygh, *p_WinT, *p_w2T, *p_WoutT;
    cudaGetSymbolAddress((void**)&p_xnh,   g_xnh);
    cudaGetSymbolAddress((void**)&p_u2h,   g_u2h);
    cudaGetSymbolAddress((void**)&p_ygh,   g_ygh);
    cudaGetSymbolAddress((void**)&p_WinT,  g_WinT);
    cudaGetSymbolAddress((void**)&p_w2T,   g_w2T);
    cudaGetSymbolAddress((void**)&p_WoutT, g_WoutT);

    const int SMB = 4*(128+128)*40*2;          // 81920: 4-stage pipeline
    const int SMO = SMB;                       // MODE5 epilogue needs 68096 <= SMB
    cudaFuncSetAttribute(gemm_mma<1>, cudaFuncAttributeMaxDynamicSharedMemorySize, SMB);
    cudaFuncSetAttribute(gemm_mma<4>, cudaFuncAttributeMaxDynamicSharedMemorySize, SMB);
    cudaFuncSetAttribute(gemm_mma<5>, cudaFuncAttributeMaxDynamicSharedMemorySize, SMO);

    // launch index (ncu captures index 3 = G2):
    prep_kernel<<<720, 256>>>(x, ln_g, ln_b, W_in, W_out, W_xproj, W_dt);  // 0
    gemm_mma<1><<<dim3(8, 64), 256, SMB>>>(                                // 1  G1
        p_xnh, p_WinT, nullptr, nullptr, CDIM);
    conv_silu_kernel<<<NROWS, 256>>>(conv_w, conv_b);                      // 2
    gemm_mma<4><<<dim3(5, 64), 256, SMB>>>(                                // 3  G2+G3
        p_u2h, p_w2T, nullptr, b_dt, DINNER);
    scan_kernel<<<256, 256>>>(A_log, D_skip);                              // 4
    gemm_mma<5><<<dim3(2, 64), 256, SMO>>>(                                // 5  G4+out
        p_ygh, p_WoutT, out, x, DINNER);
}

// round 15
// speedup vs baseline: 1.0034x; 1.0034x over previous
#include <cuda_runtime.h>
#include <cuda_bf16.h>
#include <math.h>
#include <stdint.h>

// ---------------- problem constants ----------------
#define LSEQ   1024
#define BATCH  8
#define CDIM   256
#define DINNER 512
#define DSTATE 16
#define NROWS  (BATCH*LSEQ)   // 8192

typedef __nv_bfloat16 bf16;
typedef __nv_bfloat162 bf162;
typedef unsigned long long u64;

// ---------------- scratch (static, no allocs) ----------------
__device__ __align__(256) bf16     g_xnh  [(size_t)NROWS*CDIM];
__device__ __align__(256) bf16     g_uh   [(size_t)NROWS*DINNER];
__device__ __align__(256) bf16     g_gzh  [(size_t)NROWS*DINNER];   // silu(z), [row][d]
__device__ __align__(256) bf16     g_u2h  [(size_t)NROWS*DINNER];
__device__ __align__(256) uint32_t g_du   [(size_t)NROWS*DINNER];   // (dt,u2) pack, [row][d]
__device__ __align__(256) float4   g_bc4  [(size_t)NROWS*8];        // (B_s,B_s+8,C_s,C_s+8)
__device__ __align__(256) bf16     g_ygh  [(size_t)NROWS*DINNER];   // [row][d]
// weights, bf16, K-major [N][K]
__device__ __align__(256) bf16     g_WinT  [(size_t)1024*CDIM];
__device__ __align__(256) bf16     g_w2T   [(size_t)640*DINNER];    // [0:512)=wcomb, [512:544)=Wbc, rest 0
__device__ __align__(256) bf16     g_WoutT [(size_t)CDIM*DINNER];

// ---------------- small helpers ----------------
__device__ __forceinline__ float siluf(float v) { return v / (1.f + __expf(-v)); }
__device__ __forceinline__ float softplusf(float v) {
    return (v > 20.f) ? v : log1pf(__expf(v));
}
__device__ __forceinline__ uint32_t pbf2(float lo, float hi) {
    uint32_t r;
    asm("cvt.rn.bf16x2.f32 %0, %1, %2;" : "=r"(r) : "f"(hi), "f"(lo));
    return r;
}
__device__ __forceinline__ uint32_t smem_u32(const void* p) {
    return (uint32_t)__cvta_generic_to_shared(p);
}
__device__ __forceinline__ void cp16(uint32_t sm, const void* gm) {
    asm volatile("cp.async.cg.shared.global [%0], [%1], 16;\n" :: "r"(sm), "l"(gm));
}
__device__ __forceinline__ void ldsm4(uint32_t* r, uint32_t addr) {
    asm volatile("ldmatrix.sync.aligned.m8n8.x4.shared.b16 {%0,%1,%2,%3}, [%4];"
        : "=r"(r[0]), "=r"(r[1]), "=r"(r[2]), "=r"(r[3]) : "r"(addr));
}
__device__ __forceinline__ void mma16(float* c, const uint32_t* a, const uint32_t* b) {
    asm volatile(
        "mma.sync.aligned.m16n8k16.row.col.f32.bf16.bf16.f32 "
        "{%0,%1,%2,%3}, {%4,%5,%6,%7}, {%8,%9}, {%0,%1,%2,%3};\n"
        : "+f"(c[0]), "+f"(c[1]), "+f"(c[2]), "+f"(c[3])
        : "r"(a[0]), "r"(a[1]), "r"(a[2]), "r"(a[3]), "r"(b[0]), "r"(b[1]));
}
// ---- packed f32x2 (Blackwell base ISA) ----
__device__ __forceinline__ u64 pk2(float lo, float hi) {
    u64 r; asm("mov.b64 %0, {%1, %2};" : "=l"(r) : "f"(lo), "f"(hi)); return r;
}
__device__ __forceinline__ void upk2(float& lo, float& hi, u64 v) {
    asm("mov.b64 {%0, %1}, %2;" : "=f"(lo), "=f"(hi) : "l"(v));
}
__device__ __forceinline__ u64 mul2(u64 a, u64 b) {
    u64 r; asm("mul.rn.f32x2 %0, %1, %2;" : "=l"(r) : "l"(a), "l"(b)); return r;
}
__device__ __forceinline__ u64 add2(u64 a, u64 b) {
    u64 r; asm("add.rn.f32x2 %0, %1, %2;" : "=l"(r) : "l"(a), "l"(b)); return r;
}
__device__ __forceinline__ u64 fma2(u64 a, u64 b, u64 c) {
    u64 r; asm("fma.rn.f32x2 %0, %1, %2, %3;" : "=l"(r) : "l"(a), "l"(b), "l"(c)); return r;
}
__device__ __forceinline__ float ex2f(float x) {
    float r; asm("ex2.approx.f32 %0, %1;" : "=f"(r) : "f"(x)); return r;
}

// ---------------- merged prep kernel: ln + prepA + prepBW ----------
__device__ __forceinline__ void tconv_body(char* smc, const float* src, bf16* dst,
                                           int K, int ldsrc, int coloff,
                                           int n0, int k0, int t) {
    float (*sm)[33] = (float(*)[33])smc;
    #pragma unroll
    for (int p = 0; p < 4; p++) {
        int ki = p*8 + (t >> 5);
        sm[ki][t & 31] = src[(size_t)(k0+ki)*ldsrc + coloff + n0 + (t & 31)];
    }
    __syncthreads();
    #pragma unroll
    for (int p = 0; p < 4; p++) {
        int ni = p*8 + (t >> 5);
        dst[(size_t)(n0+ni)*K + k0 + (t & 31)] = __float2bfloat16(sm[t & 31][ni]);
    }
}

__global__ __launch_bounds__(256) void prep_kernel(
    const float* __restrict__ x, const float* __restrict__ gamma,
    const float* __restrict__ beta, const float* __restrict__ W_in,
    const float* __restrict__ W_out, const float* __restrict__ W_xproj,
    const float* __restrict__ W_dt)
{
    __shared__ __align__(16) char smc[35840];
    const int bid = blockIdx.x, t = threadIdx.x;
    if (bid < 256) {
        float* sm   = (float*)smc;
        float* s_mu = sm + 32*257;
        float* s_rs = s_mu + 32;
        const int b  = bid >> 5;
        const int l0 = (bid & 31) * 32;
        #pragma unroll
        for (int j = 0; j < 32; j++) {
            int e = j*256 + t;
            sm[(e & 31)*257 + (e >> 5)] =
                x[((size_t)(b*CDIM + (e >> 5)))*LSEQ + l0 + (e & 31)];
        }
        __syncthreads();
        const int w = t >> 5, lane = t & 31;
        #pragma unroll
        for (int q = 0; q < 4; q++) {
            int li = w*4 + q;
            float s = 0.f, s2 = 0.f;
            #pragma unroll
            for (int j = 0; j < 8; j++) {
                float v = sm[li*257 + lane + j*32];
                s += v; s2 = fmaf(v, v, s2);
            }
            #pragma unroll
            for (int o = 16; o; o >>= 1) {
                s  += __shfl_xor_sync(0xffffffffu, s,  o);
                s2 += __shfl_xor_sync(0xffffffffu, s2, o);
            }
            if (lane == 0) {
                float mu = s * (1.f/CDIM);
                s_mu[li] = mu;
                s_rs[li] = rsqrtf(s2 * (1.f/CDIM) - mu*mu + 1e-5f);
            }
        }
        __syncthreads();
        const float g = gamma[t], be = beta[t];
        #pragma unroll
        for (int li = 0; li < 32; li++) {
            float v = (sm[li*257 + t] - s_mu[li]) * s_rs[li];
            g_xnh[((size_t)(b*LSEQ + l0 + li))*CDIM + t] =
                __float2bfloat16(fmaf(v, g, be));
        }
    } else if (bid < 512) {
        int i = bid - 256;
        tconv_body(smc, W_in, g_WinT, CDIM, 1024, 0, (i & 31)*32, (i >> 5)*32, t);
    } else if (bid < 640) {
        int i = bid - 512;
        tconv_body(smc, W_out, g_WoutT, DINNER, 256, 0, (i & 7)*32, (i >> 3)*32, t);
    } else if (bid < 656) {
        tconv_body(smc, W_xproj, g_w2T + (size_t)512*DINNER, DINNER, 48, 16, 0,
                   (bid - 640)*32, t);
    } else {
        float (*s_wx)[17] = (float(*)[17])smc;
        float (*s_wd)[8]  = (float(*)[8])(smc + 512*17*4);
        const int wb = bid - 656;
        const int n8 = wb*8;
        #pragma unroll
        for (int i = 0; i < 32; i++) {
            int idx = t + i*256;
            s_wx[idx >> 4][idx & 15] = W_xproj[(idx >> 4)*48 + (idx & 15)];
        }
        if (t < 128) s_wd[t >> 3][t & 7] = W_dt[(t >> 3)*DINNER + n8 + (t & 7)];
        __syncthreads();
        const int w = t >> 5, lane = t & 31;
        const int n = n8 + w;
        for (int k = lane; k < DINNER; k += 32) {
            float a = 0.f;
            #pragma unroll
            for (int j = 0; j < 16; j++) a = fmaf(s_wx[k][j], s_wd[j][w], a);
            g_w2T[(size_t)n*DINNER + k] = __float2bfloat16(a);
        }
        uint32_t* zp = (uint32_t*)(g_w2T + (size_t)544*DINNER);
        int i0 = wb*384 + t;
        zp[i0] = 0;
        if (t < 128) zp[i0 + 256] = 0;
    }
}

// ---------------- bf16 mma.sync GEMM, 3-stage cp.async (verified R13) ------------
// MODE 1: col<512 -> u bf16 (g_uh); col>=512 -> silu -> g_gzh
// MODE 4: G2+G3: n0<512 -> (dt,u2) pack -> g_du; n0==512 -> bc4 pack (wn==0)
// MODE 5: out-fused: smem-transpose fp32 tile, out[b][c][l] = v + x
template<int MODE>
__global__ __launch_bounds__(256, 2) void gemm_mma(
    const bf16* __restrict__ A, const bf16* __restrict__ Bt,
    float* __restrict__ Cf, const float* __restrict__ e0,
    int K)
{
    constexpr int BM = 128, BN = 128, WM = 64, WN = 32;
    constexpr int BK = 32, ST = 3;
    constexpr int LDA = BK + 8;
    extern __shared__ bf16 sm[];
    bf16* As = sm;
    bf16* Bs = sm + (size_t)ST*BM*LDA;
    const int tid = threadIdx.x, wid = tid >> 5, lane = tid & 31;
    const int g = lane >> 2, q = lane & 3;
    const int wm = wid >> 2, wn = wid & 3;
    const int m0 = blockIdx.y * BM, n0 = blockIdx.x * BN;
    constexpr int MF = WM / 16, NF = WN / 8;
    float acc[MF][NF][4] = {};

    auto load_stage = [&](int s, int kt) {
        const int k0 = kt * BK;
        #pragma unroll
        for (int i = 0; i < BM*4/256; i++) {
            int idx = tid + i*256;
            int r = idx >> 2, c = idx & 3;
            cp16(smem_u32(&As[(s*BM + r)*LDA + c*8]), &A[(size_t)(m0+r)*K + k0 + c*8]);
        }
        #pragma unroll
        for (int i = 0; i < BN*4/256; i++) {
            int idx = tid + i*256;
            int r = idx >> 2, c = idx & 3;
            cp16(smem_u32(&Bs[(s*BN + r)*LDA + c*8]), &Bt[(size_t)(n0+r)*K + k0 + c*8]);
        }
        asm volatile("cp.async.commit_group;\n");
    };
    auto compute = [&](int s) {
        uint32_t aB = smem_u32(As)
            + (uint32_t)(((s*BM + wm*WM + (lane & 15))*LDA + ((lane >> 4) << 3)) * 2);
        uint32_t bB = smem_u32(Bs)
            + (uint32_t)(((s*BN + wn*WN + ((lane >> 4) << 3) + (lane & 7))*LDA
                          + (((lane >> 3) & 1) << 3)) * 2);
        uint32_t af[2][MF][4], bfr[2][NF][2];
        #pragma unroll
        for (int h = 0; h < 2; h++) {
            #pragma unroll
            for (int i = 0; i < MF; i++)
                ldsm4(af[h][i], aB + (uint32_t)((i*16*LDA + h*16) * 2));
            #pragma unroll
            for (int jj = 0; jj < NF/2; jj++) {
                uint32_t tr[4];
                ldsm4(tr, bB + (uint32_t)((jj*16*LDA + h*16) * 2));
                bfr[h][2*jj][0] = tr[0]; bfr[h][2*jj][1] = tr[1];
                bfr[h][2*jj+1][0] = tr[2]; bfr[h][2*jj+1][1] = tr[3];
            }
        }
        #pragma unroll
        for (int h = 0; h < 2; h++)
            #pragma unroll
            for (int i = 0; i < MF; i++)
                #pragma unroll
                for (int j = 0; j < NF; j++)
                    mma16(acc[i][j], af[h][i], bfr[h][j]);
    };

    const int nk = K / BK;
    load_stage(0, 0);
    load_stage(1, 1);
    #pragma unroll 1
    for (int kt = 0; kt < nk; kt++) {
        asm volatile("cp.async.wait_group 1;\n");
        __syncthreads();
        int nx = kt + 2;
        if (nx < nk) load_stage(nx % ST, nx);
        else asm volatile("cp.async.commit_group;\n");
        compute(kt % ST);
    }

    // ----- epilogues -----
    if (MODE == 5) {
        __syncthreads();
        float* smt = (float*)sm;   // 128 x 133 fp32
        #pragma unroll
        for (int i = 0; i < MF; i++) {
            int r = wm*WM + i*16 + g;
            #pragma unroll
            for (int j = 0; j < NF; j++) {
                int c = wn*WN + j*8 + 2*q;
                smt[(size_t)r*133 + c]       = acc[i][j][0];
                smt[(size_t)r*133 + c + 1]   = acc[i][j][1];
                smt[(size_t)(r+8)*133 + c]   = acc[i][j][2];
                smt[(size_t)(r+8)*133 + c+1] = acc[i][j][3];
            }
        }
        __syncthreads();
        const int b = m0 >> 10, l0 = m0 & 1023;
        #pragma unroll 4
        for (int i = 0; i < 64; i++) {
            int idx = tid + i*256;
            int c = idx >> 7, l = idx & 127;
            size_t oi = ((size_t)(b*CDIM + n0 + c))*LSEQ + l0 + l;
            Cf[oi] = smt[(size_t)l*133 + c] + e0[oi];
        }
        return;
    }
    #pragma unroll
    for (int i = 0; i < MF; i++) {
        int row = m0 + wm*WM + i*16 + g;
        if (MODE == 1) {
            #pragma unroll
            for (int j = 0; j < NF; j++) {
                int col = n0 + wn*WN + j*8 + 2*q;
                float v0 = acc[i][j][0], v1 = acc[i][j][1];
                float v2 = acc[i][j][2], v3 = acc[i][j][3];
                if (col < DINNER) {
                    *(uint32_t*)&g_uh[(size_t)(row  )*DINNER + col] = pbf2(v0, v1);
                    *(uint32_t*)&g_uh[(size_t)(row+8)*DINNER + col] = pbf2(v2, v3);
                } else {
                    int cz = col - DINNER;
                    *(uint32_t*)&g_gzh[(size_t)(row  )*DINNER + cz] =
                        pbf2(siluf(v0), siluf(v1));
                    *(uint32_t*)&g_gzh[(size_t)(row+8)*DINNER + cz] =
                        pbf2(siluf(v2), siluf(v3));
                }
            }
        } else if (MODE == 4) {
            if (n0 < DINNER) {
                #pragma unroll
                for (int j = 0; j < NF; j++) {
                    int col = n0 + wn*WN + j*8 + 2*q;
                    float v0 = acc[i][j][0], v1 = acc[i][j][1];
                    float v2 = acc[i][j][2], v3 = acc[i][j][3];
                    float b0 = e0[col], b1 = e0[col+1];
                    uint32_t ua = *(const uint32_t*)&g_u2h[(size_t)(row  )*DINNER + col];
                    uint32_t ub = *(const uint32_t*)&g_u2h[(size_t)(row+8)*DINNER + col];
                    uint32_t d0 = (uint32_t)__bfloat16_as_ushort(__float2bfloat16(softplusf(v0 + b0)));
                    uint32_t d1 = (uint32_t)__bfloat16_as_ushort(__float2bfloat16(softplusf(v1 + b1)));
                    uint32_t d2 = (uint32_t)__bfloat16_as_ushort(__float2bfloat16(softplusf(v2 + b0)));
                    uint32_t d3 = (uint32_t)__bfloat16_as_ushort(__float2bfloat16(softplusf(v3 + b1)));
                    uint2 wa = make_uint2(d0 | ((ua & 0xFFFFu) << 16), d1 | (ua & 0xFFFF0000u));
                    uint2 wb = make_uint2(d2 | ((ub & 0xFFFFu) << 16), d3 | (ub & 0xFFFF0000u));
                    *(uint2*)&g_du[(size_t)(row  )*DINNER + col] = wa;
                    *(uint2*)&g_du[(size_t)(row+8)*DINNER + col] = wb;
                }
            } else if (wn == 0) {
                // bc4 pack: (B_sp, B_sp+8, C_sp, C_sp+8); B = cols 0..15, C = cols 16..31
                // lane (g,q): cols 2q,2q+1 per j; sp=2q -> elems [0], sp=2q+1 -> [1]; rows+8 -> [2],[3]
                g_bc4[(size_t)(row  )*8 + 2*q]     = make_float4(acc[i][0][0], acc[i][1][0], acc[i][2][0], acc[i][3][0]);
                g_bc4[(size_t)(row  )*8 + 2*q + 1] = make_float4(acc[i][0][1], acc[i][1][1], acc[i][2][1], acc[i][3][1]);
                g_bc4[(size_t)(row+8)*8 + 2*q]     = make_float4(acc[i][0][2], acc[i][1][2], acc[i][2][2], acc[i][3][2]);
                g_bc4[(size_t)(row+8)*8 + 2*q + 1] = make_float4(acc[i][0][3], acc[i][1][3], acc[i][2][3], acc[i][3][3]);
            }
        }
    }
}

// ---------------- depthwise causal conv (D_CONV=4) + SiLU, bf162 ----------------
__global__ __launch_bounds__(256) void conv_silu_kernel(const float* __restrict__ cw,
                                                        const float* __restrict__ cb) {
    int gid = blockIdx.x*256 + threadIdx.x;
    int d2  = gid & 255;
    int row = gid >> 8;
    int l   = row & (LSEQ-1);
    int d   = d2 * 2;
    float a0 = cb[d], a1 = cb[d+1];
    const uint32_t* up = (const uint32_t*)g_uh;
    #pragma unroll
    for (int k = 0; k < 4; k++) {
        int ll = l - 3 + k;
        if (ll >= 0) {
            uint32_t w = up[(size_t)(row - 3 + k)*256 + d2];
            bf162 p = *(bf162*)&w;
            a0 = fmaf(__bfloat162float(p.x), cw[d*4 + k],     a0);
            a1 = fmaf(__bfloat162float(p.y), cw[(d+1)*4 + k], a1);
        }
    }
    ((uint32_t*)g_u2h)[gid] = pbf2(siluf(a0), siluf(a1));
}

// ---------------- selective scan v6: f32x2 packed, 4 chains/warp ----------------
// 128 threads = 4 warps; warp = 4 chains x 8 lanes; lane owns states (sp, sp+8)
// packed in f32x2. Block covers batch b, channels dblk..dblk+15, chunked 16 steps.
__global__ __launch_bounds__(128) void scan_kernel(const float* __restrict__ A_log,
                                                   const float* __restrict__ D_skip) {
    __shared__ uint2          s_du[2][16][8];     // (dt,u2) pairs: [l][dd] covers d pairs
    __shared__ uint32_t       s_gz[2][16][8];     // gz u16 pairs
    __shared__ float4         s_bc4[2][16][8];    // (B_sp,B_sp8,C_sp,C_sp8) per [l][sp]
    __shared__ uint32_t       s_yg[2][16][8];     // yg u16 pairs
    __shared__ u64            s_p[4][4*137];      // per warp, per chain (stride 137)
    const int b    = blockIdx.x >> 5;
    const int dblk = (blockIdx.x & 31) * 16;
    const int tid  = threadIdx.x;
    const int widx = tid >> 5, lane = tid & 31;
    const int ci   = lane >> 3, sp = lane & 7;
    const int ch   = widx*4 + ci;                 // 0..15
    const int d    = dblk + ch;
    const float L2E = 1.4426950408889634f;
    const float Av0 = -__expf(A_log[d*DSTATE + sp])     * L2E;
    const float Av1 = -__expf(A_log[d*DSTATE + sp + 8]) * L2E;
    const float Dd  = D_skip[d];
    const size_t rb = (size_t)b * LSEQ;
    const int li = tid >> 3, dd = tid & 7;        // tile fill/flush: 16 x 8
    u64* pch = &s_p[widx][ci*137];

    uint2 r_du; uint32_t r_gz; float4 r_bc;
    auto ldchunk = [&](int c0) {
        size_t rw = rb + c0 + li;
        r_du = *(const uint2*)&g_du[rw*DINNER + dblk + dd*2];
        r_gz = *(const uint32_t*)&((const unsigned short*)g_gzh)[rw*DINNER + dblk + dd*2];
        r_bc = g_bc4[rw*8 + dd];
    };
    u64 h2 = 0;
    ldchunk(0);
    #pragma unroll 1
    for (int k = 0; k < 64; k++) {
        const int cb = k & 1;
        s_du[cb][li][dd] = r_du;
        s_gz[cb][li][dd] = r_gz;
        s_bc4[cb][li][dd] = r_bc;
        __syncthreads();
        if (k > 0)
            ((uint32_t*)g_ygh)[((rb + (k-1)*16 + li)*DINNER + dblk)/2 + dd] =
                s_yg[cb ^ 1][li][dd];
        if (k < 63) ldchunk((k+1)*16);
        // Phase A: packed recurrence
        u64 p2[16];
        #pragma unroll
        for (int j = 0; j < 16; j++) {
            uint32_t w = ((const uint32_t*)&s_du[cb][j][0])[ch];
            bf162 pk = *(bf162*)&w;
            float dt = __bfloat162float(pk.x);
            float u2 = __bfloat162float(pk.y);
            float dA0 = ex2f(dt * Av0);
            float dA1 = ex2f(dt * Av1);
            float coef = dt * u2;
            float4 bc = s_bc4[cb][j][sp];
            u64 B2 = pk2(bc.x, bc.y);
            u64 C2 = pk2(bc.z, bc.w);
            h2 = fma2(pk2(dA0, dA1), h2, mul2(B2, pk2(coef, coef)));
            p2[j] = mul2(h2, C2);
        }
        // Phase B: smem transpose-reduce over states (8 lanes x 2 halves)
        #pragma unroll
        for (int j = 0; j < 16; j++) pch[sp*17 + j] = p2[j];
        __syncwarp();
        float y0, y1;
        {
            u64 q = add2(add2(add2(pch[0*17+sp], pch[1*17+sp]),
                              add2(pch[2*17+sp], pch[3*17+sp])),
                         add2(add2(pch[4*17+sp], pch[5*17+sp]),
                              add2(pch[6*17+sp], pch[7*17+sp])));
            float lo, hi; upk2(lo, hi, q); y0 = lo + hi;
        }
        {
            int c2 = sp + 8;
            u64 q = add2(add2(add2(pch[0*17+c2], pch[1*17+c2]),
                              add2(pch[2*17+c2], pch[3*17+c2])),
                         add2(add2(pch[4*17+c2], pch[5*17+c2]),
                              add2(pch[6*17+c2], pch[7*17+c2])));
            float lo, hi; upk2(lo, hi, q); y1 = lo + hi;
        }
        // Phase C: lane finalizes steps j = sp and j = sp+8 for its channel
        #pragma unroll
        for (int half = 0; half < 2; half++) {
            int jj = sp + half*8;
            float yv = half ? y1 : y0;
            uint32_t w = ((const uint32_t*)&s_du[cb][jj][0])[ch];
            bf162 pk = *(bf162*)&w;
            float u2 = __bfloat162float(pk.y);
            unsigned short gs = ((const unsigned short*)&s_gz[cb][jj][0])[ch];
            float gzf = __bfloat162float(__ushort_as_bfloat16(gs));
            float outv = (yv + u2 * Dd) * gzf;
            ((unsigned short*)&s_yg[cb][jj][0])[ch] =
                __bfloat16_as_ushort(__float2bfloat16(outv));
        }
    }
    __syncthreads();
    ((uint32_t*)g_ygh)[((rb + 63*16 + li)*DINNER + dblk)/2 + dd] = s_yg[1][li][dd];
}

// ---------------- host launch ----------------
extern "C" void kernel_launch(void* const* d_in, const int* in_sizes, int n_in,
                              void* d_out, int out_size) {
    const float* x       = (const float*)d_in[0];
    const float* ln_g    = (const float*)d_in[1];
    const float* ln_b    = (const float*)d_in[2];
    const float* W_in    = (const float*)d_in[3];
    const float* conv_w  = (const float*)d_in[4];
    const float* conv_b  = (const float*)d_in[5];
    const float* W_xproj = (const float*)d_in[6];
    const float* W_dt    = (const float*)d_in[7];
    const float* b_dt    = (const float*)d_in[8];
    const float* A_log   = (const float*)d_in[9];
    const float* D_skip  = (const float*)d_in[10];
    const float* W_out   = (const float*)d_in[11];
    float* out = (float*)d_out;

    bf16 *p_xnh, *p_u2h, *p_ygh, *p_WinT, *p_w2T, *p_WoutT;
    cudaGetSymbolAddress((void**)&p_xnh,   g_xnh);
    cudaGetSymbolAddress((void**)&p_u2h,   g_u2h);
    cudaGetSymbolAddress((void**)&p_ygh,   g_ygh);
    cudaGetSymbolAddress((void**)&p_WinT,  g_WinT);
    cudaGetSymbolAddress((void**)&p_w2T,   g_w2T);
    cudaGetSymbolAddress((void**)&p_WoutT, g_WoutT);

    const int SMB = 3*(128+128)*40*2;          // 61440 pipeline (R13 verified)
    const int SMO = 128*133*4;                 // 68096 for MODE 5
    cudaFuncSetAttribute(gemm_mma<1>, cudaFuncAttributeMaxDynamicSharedMemorySize, SMB);
    cudaFuncSetAttribute(gemm_mma<4>, cudaFuncAttributeMaxDynamicSharedMemorySize, SMB);
    cudaFuncSetAttribute(gemm_mma<5>, cudaFuncAttributeMaxDynamicSharedMemorySize, SMO);

    // launch index (ncu captures index 3 = G2):
    prep_kernel<<<720, 256>>>(x, ln_g, ln_b, W_in, W_out, W_xproj, W_dt);  // 0
    gemm_mma<1><<<dim3(8, 64), 256, SMB>>>(                                // 1  G1
        p_xnh, p_WinT, nullptr, nullptr, CDIM);
    conv_silu_kernel<<<NROWS, 256>>>(conv_w, conv_b);                      // 2
    gemm_mma<4><<<dim3(5, 64), 256, SMB>>>(                                // 3  G2+G3
        p_u2h, p_w2T, nullptr, b_dt, DINNER);
    scan_kernel<<<256, 128>>>(A_log, D_skip);                              // 4
    gemm_mma<5><<<dim3(2, 64), 256, SMO>>>(                                // 5  G4+out
        p_ygh, p_WoutT, out, x, DINNER);
}

// round 17
// speedup vs baseline: 1.0381x; 1.0346x over previous
#include <cuda_runtime.h>
#include <cuda_bf16.h>
#include <math.h>
#include <stdint.h>

// ---------------- problem constants ----------------
#define LSEQ   1024
#define BATCH  8
#define CDIM   256
#define DINNER 512
#define DSTATE 16
#define NROWS  (BATCH*LSEQ)   // 8192

typedef __nv_bfloat16 bf16;
typedef __nv_bfloat162 bf162;

// ---------------- scratch (static, no allocs) ----------------
__device__ __align__(256) bf16     g_xnh  [(size_t)NROWS*CDIM];
__device__ __align__(256) bf16     g_uh   [(size_t)NROWS*DINNER];
__device__ __align__(256) bf16     g_gzh  [(size_t)NROWS*DINNER];   // silu(z), [row][d]
__device__ __align__(256) bf16     g_u2h  [(size_t)NROWS*DINNER];
__device__ __align__(256) uint32_t g_du   [(size_t)NROWS*DINNER];   // (dt,u2) pack, [row][d]
__device__ __align__(256) float2   g_bc   [(size_t)NROWS*DSTATE];   // [row][s] = (B_s, C_s)
__device__ __align__(256) float    g_dbc  [(size_t)NROWS*48];       // u2 @ W_xproj, fp32
__device__ __align__(256) bf16     g_ygh  [(size_t)NROWS*DINNER];   // [row][d]
// weights, bf16, K-major [N][K]
__device__ __align__(256) bf16     g_WinT  [(size_t)1024*CDIM];
__device__ __align__(256) bf16     g_w3T   [(size_t)128*DINNER];    // W_xprojT rows 0..47, rest 0
__device__ __align__(256) bf16     g_WdtT  [(size_t)512*16];        // W_dtT [n][k]
__device__ __align__(256) bf16     g_WoutT [(size_t)CDIM*DINNER];

// ---------------- small helpers ----------------
__device__ __forceinline__ float siluf(float v) { return v / (1.f + __expf(-v)); }
__device__ __forceinline__ float softplusf(float v) {
    return (v > 20.f) ? v : log1pf(__expf(v));
}
__device__ __forceinline__ uint32_t pbf2(float lo, float hi) {
    uint32_t r;
    asm("cvt.rn.bf16x2.f32 %0, %1, %2;" : "=r"(r) : "f"(hi), "f"(lo));
    return r;
}
__device__ __forceinline__ uint32_t smem_u32(const void* p) {
    return (uint32_t)__cvta_generic_to_shared(p);
}
__device__ __forceinline__ void cp16(uint32_t sm, const void* gm) {
    asm volatile("cp.async.cg.shared.global [%0], [%1], 16;\n" :: "r"(sm), "l"(gm));
}
__device__ __forceinline__ void ldsm4(uint32_t* r, uint32_t addr) {
    asm volatile("ldmatrix.sync.aligned.m8n8.x4.shared.b16 {%0,%1,%2,%3}, [%4];"
        : "=r"(r[0]), "=r"(r[1]), "=r"(r[2]), "=r"(r[3]) : "r"(addr));
}
__device__ __forceinline__ void mma16(float* c, const uint32_t* a, const uint32_t* b) {
    asm volatile(
        "mma.sync.aligned.m16n8k16.row.col.f32.bf16.bf16.f32 "
        "{%0,%1,%2,%3}, {%4,%5,%6,%7}, {%8,%9}, {%0,%1,%2,%3};\n"
        : "+f"(c[0]), "+f"(c[1]), "+f"(c[2]), "+f"(c[3])
        : "r"(a[0]), "r"(a[1]), "r"(a[2]), "r"(a[3]), "r"(b[0]), "r"(b[1]));
}

// ---------------- merged prep kernel ----------
// blocks 0..255   : LayerNorm -> g_xnh
// blocks 256..511 : W_in -> WinT
// blocks 512..639 : W_out -> WoutT
// blocks 640..703 : W_xproj -> w3T (guarded: src col < 48 else 0)
// block  704      : W_dt -> WdtT
__device__ __forceinline__ void tconv_body(char* smc, const float* src, bf16* dst,
                                           int K, int ldsrc, int coloff,
                                           int n0, int k0, int t) {
    float (*sm)[33] = (float(*)[33])smc;
    #pragma unroll
    for (int p = 0; p < 4; p++) {
        int ki = p*8 + (t >> 5);
        sm[ki][t & 31] = src[(size_t)(k0+ki)*ldsrc + coloff + n0 + (t & 31)];
    }
    __syncthreads();
    #pragma unroll
    for (int p = 0; p < 4; p++) {
        int ni = p*8 + (t >> 5);
        dst[(size_t)(n0+ni)*K + k0 + (t & 31)] = __float2bfloat16(sm[t & 31][ni]);
    }
}

__global__ __launch_bounds__(256) void prep_kernel(
    const float* __restrict__ x, const float* __restrict__ gamma,
    const float* __restrict__ beta, const float* __restrict__ W_in,
    const float* __restrict__ W_out, const float* __restrict__ W_xproj,
    const float* __restrict__ W_dt)
{
    __shared__ __align__(16) char smc[33280];   // LN branch needs 33152 bytes
    const int bid = blockIdx.x, t = threadIdx.x;
    if (bid < 256) {
        float* sm   = (float*)smc;
        float* s_mu = sm + 32*257;
        float* s_rs = s_mu + 32;
        const int b  = bid >> 5;
        const int l0 = (bid & 31) * 32;
        #pragma unroll
        for (int j = 0; j < 32; j++) {
            int e = j*256 + t;
            sm[(e & 31)*257 + (e >> 5)] =
                x[((size_t)(b*CDIM + (e >> 5)))*LSEQ + l0 + (e & 31)];
        }
        __syncthreads();
        const int w = t >> 5, lane = t & 31;
        #pragma unroll
        for (int q = 0; q < 4; q++) {
            int li = w*4 + q;
            float s = 0.f, s2 = 0.f;
            #pragma unroll
            for (int j = 0; j < 8; j++) {
                float v = sm[li*257 + lane + j*32];
                s += v; s2 = fmaf(v, v, s2);
            }
            #pragma unroll
            for (int o = 16; o; o >>= 1) {
                s  += __shfl_xor_sync(0xffffffffu, s,  o);
                s2 += __shfl_xor_sync(0xffffffffu, s2, o);
            }
            if (lane == 0) {
                float mu = s * (1.f/CDIM);
                s_mu[li] = mu;
                s_rs[li] = rsqrtf(s2 * (1.f/CDIM) - mu*mu + 1e-5f);
            }
        }
        __syncthreads();
        const float g = gamma[t], be = beta[t];
        #pragma unroll
        for (int li = 0; li < 32; li++) {
            float v = (sm[li*257 + t] - s_mu[li]) * s_rs[li];
            g_xnh[((size_t)(b*LSEQ + l0 + li))*CDIM + t] =
                __float2bfloat16(fmaf(v, g, be));
        }
    } else if (bid < 512) {
        int i = bid - 256;
        tconv_body(smc, W_in, g_WinT, CDIM, 1024, 0, (i & 31)*32, (i >> 5)*32, t);
    } else if (bid < 640) {
        int i = bid - 512;
        tconv_body(smc, W_out, g_WoutT, DINNER, 256, 0, (i & 7)*32, (i >> 3)*32, t);
    } else if (bid < 704) {
        // w3T: dst[n][k] = (n < 48) ? W_xproj[k*48 + n] : 0
        int i = bid - 640;
        int n0 = (i & 3)*32, k0 = (i >> 2)*32;
        float (*sm)[33] = (float(*)[33])smc;
        #pragma unroll
        for (int p = 0; p < 4; p++) {
            int ki = p*8 + (t >> 5);
            int nc = n0 + (t & 31);
            sm[ki][t & 31] = (nc < 48) ? W_xproj[(size_t)(k0+ki)*48 + nc] : 0.f;
        }
        __syncthreads();
        #pragma unroll
        for (int p = 0; p < 4; p++) {
            int ni = p*8 + (t >> 5);
            g_w3T[(size_t)(n0+ni)*DINNER + k0 + (t & 31)] =
                __float2bfloat16(sm[t & 31][ni]);
        }
    } else {
        // WdtT[n][k] = W_dt[k][n]
        for (int i = t; i < 512*16; i += 256) {
            int n = i >> 4, k = i & 15;
            g_WdtT[i] = __float2bfloat16(W_dt[(size_t)k*DINNER + n]);
        }
    }
}

// ---------------- bf16 mma.sync GEMM, 3-stage cp.async (verified R13) ------------
// MODE 1: G1: col<512 -> u bf16 (g_uh); col>=512 -> silu -> g_gzh
// MODE 5: G4 out-fused: smem-transpose fp32 tile, out[b][c][l] = v + x
// MODE 6: GEMM-A: fp32 dbc[row][col], col<48 (warps wn>=2 skip compute)
template<int MODE>
__global__ __launch_bounds__(256, 2) void gemm_mma(
    const bf16* __restrict__ A, const bf16* __restrict__ Bt,
    float* __restrict__ Cf, const float* __restrict__ e0,
    int K)
{
    constexpr int BM = 128, BN = 128, WM = 64, WN = 32;
    constexpr int BK = 32, ST = 3;
    constexpr int LDA = BK + 8;
    extern __shared__ bf16 sm[];
    bf16* As = sm;
    bf16* Bs = sm + (size_t)ST*BM*LDA;
    const int tid = threadIdx.x, wid = tid >> 5, lane = tid & 31;
    const int g = lane >> 2, q = lane & 3;
    const int wm = wid >> 2, wn = wid & 3;
    const int m0 = blockIdx.y * BM, n0 = blockIdx.x * BN;
    constexpr int MF = WM / 16, NF = WN / 8;
    float acc[MF][NF][4] = {};
    const bool active = !(MODE == 6 && wn >= 2);   // cols >= 64 unused in MODE 6

    auto load_stage = [&](int s, int kt) {
        const int k0 = kt * BK;
        #pragma unroll
        for (int i = 0; i < BM*4/256; i++) {
            int idx = tid + i*256;
            int r = idx >> 2, c = idx & 3;
            cp16(smem_u32(&As[(s*BM + r)*LDA + c*8]), &A[(size_t)(m0+r)*K + k0 + c*8]);
        }
        #pragma unroll
        for (int i = 0; i < BN*4/256; i++) {
            int idx = tid + i*256;
            int r = idx >> 2, c = idx & 3;
            cp16(smem_u32(&Bs[(s*BN + r)*LDA + c*8]), &Bt[(size_t)(n0+r)*K + k0 + c*8]);
        }
        asm volatile("cp.async.commit_group;\n");
    };
    auto compute = [&](int s) {
        uint32_t aB = smem_u32(As)
            + (uint32_t)(((s*BM + wm*WM + (lane & 15))*LDA + ((lane >> 4) << 3)) * 2);
        uint32_t bB = smem_u32(Bs)
            + (uint32_t)(((s*BN + wn*WN + ((lane >> 4) << 3) + (lane & 7))*LDA
                          + (((lane >> 3) & 1) << 3)) * 2);
        uint32_t af[2][MF][4], bfr[2][NF][2];
        #pragma unroll
        for (int h = 0; h < 2; h++) {
            #pragma unroll
            for (int i = 0; i < MF; i++)
                ldsm4(af[h][i], aB + (uint32_t)((i*16*LDA + h*16) * 2));
            #pragma unroll
            for (int jj = 0; jj < NF/2; jj++) {
                uint32_t tr[4];
                ldsm4(tr, bB + (uint32_t)((jj*16*LDA + h*16) * 2));
                bfr[h][2*jj][0] = tr[0]; bfr[h][2*jj][1] = tr[1];
                bfr[h][2*jj+1][0] = tr[2]; bfr[h][2*jj+1][1] = tr[3];
            }
        }
        #pragma unroll
        for (int h = 0; h < 2; h++)
            #pragma unroll
            for (int i = 0; i < MF; i++)
                #pragma unroll
                for (int j = 0; j < NF; j++)
                    mma16(acc[i][j], af[h][i], bfr[h][j]);
    };

    const int nk = K / BK;
    load_stage(0, 0);
    load_stage(1, 1);
    #pragma unroll 1
    for (int kt = 0; kt < nk; kt++) {
        asm volatile("cp.async.wait_group 1;\n");
        __syncthreads();
        int nx = kt + 2;
        if (nx < nk) load_stage(nx % ST, nx);
        else asm volatile("cp.async.commit_group;\n");
        if (active) compute(kt % ST);
    }

    // ----- epilogues -----
    if (MODE == 5) {
        __syncthreads();
        float* smt = (float*)sm;   // 128 x 133 fp32
        #pragma unroll
        for (int i = 0; i < MF; i++) {
            int r = wm*WM + i*16 + g;
            #pragma unroll
            for (int j = 0; j < NF; j++) {
                int c = wn*WN + j*8 + 2*q;
                smt[(size_t)r*133 + c]       = acc[i][j][0];
                smt[(size_t)r*133 + c + 1]   = acc[i][j][1];
                smt[(size_t)(r+8)*133 + c]   = acc[i][j][2];
                smt[(size_t)(r+8)*133 + c+1] = acc[i][j][3];
            }
        }
        __syncthreads();
        const int b = m0 >> 10, l0 = m0 & 1023;
        #pragma unroll 4
        for (int i = 0; i < 64; i++) {
            int idx = tid + i*256;
            int c = idx >> 7, l = idx & 127;
            size_t oi = ((size_t)(b*CDIM + n0 + c))*LSEQ + l0 + l;
            Cf[oi] = smt[(size_t)l*133 + c] + e0[oi];
        }
        return;
    }
    #pragma unroll
    for (int i = 0; i < MF; i++) {
        int row = m0 + wm*WM + i*16 + g;
        if (MODE == 1) {
            #pragma unroll
            for (int j = 0; j < NF; j++) {
                int col = n0 + wn*WN + j*8 + 2*q;
                float v0 = acc[i][j][0], v1 = acc[i][j][1];
                float v2 = acc[i][j][2], v3 = acc[i][j][3];
                if (col < DINNER) {
                    *(uint32_t*)&g_uh[(size_t)(row  )*DINNER + col] = pbf2(v0, v1);
                    *(uint32_t*)&g_uh[(size_t)(row+8)*DINNER + col] = pbf2(v2, v3);
                } else {
                    int cz = col - DINNER;
                    *(uint32_t*)&g_gzh[(size_t)(row  )*DINNER + cz] =
                        pbf2(siluf(v0), siluf(v1));
                    *(uint32_t*)&g_gzh[(size_t)(row+8)*DINNER + cz] =
                        pbf2(siluf(v2), siluf(v3));
                }
            }
        } else if (MODE == 6) {
            if (wn < 2) {
                #pragma unroll
                for (int j = 0; j < NF; j++) {
                    int col = wn*WN + j*8 + 2*q;
                    if (col < 48) {
                        *(float2*)&g_dbc[(size_t)(row  )*48 + col] =
                            make_float2(acc[i][j][0], acc[i][j][1]);
                        *(float2*)&g_dbc[(size_t)(row+8)*48 + col] =
                            make_float2(acc[i][j][2], acc[i][j][3]);
                    }
                }
            }
        }
    }
}

// ---------------- dtbc: dt = softplus(dbc_low @ Wdt + b); pack (dt,u2); (B,C) ----
// block = 32 rows, 256 threads; thread owns col pair (2t, 2t+1)
__global__ __launch_bounds__(256) void dtbc_kernel(const float* __restrict__ b_dt) {
    __shared__ float s_db[32][49];
    const int r0 = blockIdx.x * 32;
    const int t  = threadIdx.x;
    for (int i = t; i < 32*48; i += 256) {
        int r = i / 48, c = i % 48;
        s_db[r][c] = g_dbc[(size_t)(r0 + r)*48 + c];
    }
    __syncthreads();
    // (B,C) pack: 512 items, 2 per thread
    #pragma unroll
    for (int p = 0; p < 2; p++) {
        int idx = t + p*256;
        int rr = idx >> 4, s = idx & 15;
        g_bc[(size_t)(r0 + rr)*DSTATE + s] =
            make_float2(s_db[rr][16 + s], s_db[rr][32 + s]);
    }
    // dt cols
    const int c0 = 2*t;
    float w0[16], w1[16];
    #pragma unroll
    for (int k = 0; k < 16; k++) {
        w0[k] = __bfloat162float(g_WdtT[(size_t)c0*16 + k]);
        w1[k] = __bfloat162float(g_WdtT[(size_t)(c0+1)*16 + k]);
    }
    const float bd0 = b_dt[c0], bd1 = b_dt[c0+1];
    const uint32_t* u2w = (const uint32_t*)g_u2h;
    #pragma unroll 4
    for (int r = 0; r < 32; r++) {
        float a0 = bd0, a1 = bd1;
        #pragma unroll
        for (int k = 0; k < 16; k++) {
            float v = s_db[r][k];
            a0 = fmaf(v, w0[k], a0);
            a1 = fmaf(v, w1[k], a1);
        }
        uint32_t d0 = (uint32_t)__bfloat16_as_ushort(__float2bfloat16(softplusf(a0)));
        uint32_t d1 = (uint32_t)__bfloat16_as_ushort(__float2bfloat16(softplusf(a1)));
        uint32_t uw = u2w[(size_t)(r0 + r)*256 + t];
        uint2 o = make_uint2(d0 | ((uw & 0xFFFFu) << 16), d1 | (uw & 0xFFFF0000u));
        *(uint2*)&g_du[(size_t)(r0 + r)*DINNER + c0] = o;
    }
}

// ---------------- depthwise causal conv (D_CONV=4) + SiLU, bf162 ----------------
__global__ __launch_bounds__(256) void conv_silu_kernel(const float* __restrict__ cw,
                                                        const float* __restrict__ cb) {
    int gid = blockIdx.x*256 + threadIdx.x;
    int d2  = gid & 255;
    int row = gid >> 8;
    int l   = row & (LSEQ-1);
    int d   = d2 * 2;
    float a0 = cb[d], a1 = cb[d+1];
    const uint32_t* up = (const uint32_t*)g_uh;
    #pragma unroll
    for (int k = 0; k < 4; k++) {
        int ll = l - 3 + k;
        if (ll >= 0) {
            uint32_t w = up[(size_t)(row - 3 + k)*256 + d2];
            bf162 p = *(bf162*)&w;
            a0 = fmaf(__bfloat162float(p.x), cw[d*4 + k],     a0);
            a1 = fmaf(__bfloat162float(p.y), cw[(d+1)*4 + k], a1);
        }
    }
    ((uint32_t*)g_u2h)[gid] = pbf2(siluf(a0), siluf(a1));
}

// ---------------- selective scan v5 (verified R12/R13) ----------------
__global__ __launch_bounds__(256) void scan_kernel(const float* __restrict__ A_log,
                                                   const float* __restrict__ D_skip) {
    __shared__ uint32_t       s_du[2][16][16];
    __shared__ float2         s_bc[2][16][16];
    __shared__ unsigned short s_gz[2][16][16];
    __shared__ unsigned short s_yg[2][16][16];
    __shared__ float          s_p [8][2][16][17];
    const int b    = blockIdx.x >> 5;
    const int dblk = (blockIdx.x & 31) * 16;
    const int tid  = threadIdx.x;
    const int widx = tid >> 5, lane = tid & 31;
    const int half = lane >> 4, s = lane & 15;
    const int ch   = 2*widx + half;
    const int d    = dblk + ch;
    const float Aval = -__expf(A_log[d*DSTATE + s]);
    const float Dd   = D_skip[d];
    const size_t rb  = (size_t)b * LSEQ;
    const int li = tid >> 4, dd = tid & 15;
    const uint32_t*       duG = g_du;
    const unsigned short* gzG = (const unsigned short*)g_gzh;
    unsigned short*       ygG = (unsigned short*)g_ygh;
    float* pbase = &s_p[widx][half][0][0];

    uint32_t r_du; unsigned short r_gz; float2 r_bc;
    auto ldchunk = [&](int c0) {
        size_t rw = (rb + c0 + li);
        r_du = duG[rw*DINNER + dblk + dd];
        r_gz = gzG[rw*DINNER + dblk + dd];
        r_bc = g_bc[rw*DSTATE + dd];
    };
    float h = 0.f;
    ldchunk(0);
    #pragma unroll 1
    for (int k = 0; k < 64; k++) {
        const int cb = k & 1;
        s_du[cb][li][dd] = r_du;
        s_gz[cb][li][dd] = r_gz;
        s_bc[cb][li][dd] = r_bc;
        __syncthreads();
        if (k > 0)
            ygG[(rb + (k-1)*16 + li)*DINNER + dblk + dd] = s_yg[cb ^ 1][li][dd];
        if (k < 63) ldchunk((k+1)*16);
        float p[16];
        #pragma unroll
        for (int j = 0; j < 16; j++) {
            uint32_t w = s_du[cb][j][ch];
            bf162 pk = *(bf162*)&w;
            float dt = __bfloat162float(pk.x);
            float u2 = __bfloat162float(pk.y);
            float2 bcv = s_bc[cb][j][s];
            float dA = __expf(dt * Aval);
            h = fmaf(dA, h, dt * u2 * bcv.x);
            p[j] = h * bcv.y;
        }
        #pragma unroll
        for (int j = 0; j < 16; j++) pbase[s*17 + j] = p[j];
        __syncwarp();
        float t[16];
        #pragma unroll
        for (int j2 = 0; j2 < 16; j2++) t[j2] = pbase[j2*17 + s];
        #pragma unroll
        for (int st = 1; st < 16; st <<= 1)
            #pragma unroll
            for (int j2 = 0; j2 < 16; j2 += 2*st) t[j2] += t[j2 + st];
        {
            uint32_t w = s_du[cb][s][ch];
            bf162 pk = *(bf162*)&w;
            float u2 = __bfloat162float(pk.y);
            float yv = t[0] + u2 * Dd;
            float gzf = __bfloat162float(__ushort_as_bfloat16(s_gz[cb][s][ch]));
            s_yg[cb][s][ch] = __bfloat16_as_ushort(__float2bfloat16(yv * gzf));
        }
    }
    __syncthreads();
    ygG[(rb + 63*16 + li)*DINNER + dblk + dd] = s_yg[1][li][dd];
}

// ---------------- host launch ----------------
extern "C" void kernel_launch(void* const* d_in, const int* in_sizes, int n_in,
                              void* d_out, int out_size) {
    const float* x       = (const float*)d_in[0];
    const float* ln_g    = (const float*)d_in[1];
    const float* ln_b    = (const float*)d_in[2];
    const float* W_in    = (const float*)d_in[3];
    const float* conv_w  = (const float*)d_in[4];
    const float* conv_b  = (const float*)d_in[5];
    const float* W_xproj = (const float*)d_in[6];
    const float* W_dt    = (const float*)d_in[7];
    const float* b_dt    = (const float*)d_in[8];
    const float* A_log   = (const float*)d_in[9];
    const float* D_skip  = (const float*)d_in[10];
    const float* W_out   = (const float*)d_in[11];
    float* out = (float*)d_out;

    bf16 *p_xnh, *p_u2h, *p_ygh, *p_WinT, *p_w3T, *p_WoutT;
    cudaGetSymbolAddress((void**)&p_xnh,   g_xnh);
    cudaGetSymbolAddress((void**)&p_u2h,   g_u2h);
    cudaGetSymbolAddress((void**)&p_ygh,   g_ygh);
    cudaGetSymbolAddress((void**)&p_WinT,  g_WinT);
    cudaGetSymbolAddress((void**)&p_w3T,   g_w3T);
    cudaGetSymbolAddress((void**)&p_WoutT, g_WoutT);

    const int SMB = 3*(128+128)*40*2;          // 61440 pipeline
    const int SMO = 128*133*4;                 // 68096 for MODE 5
    cudaFuncSetAttribute(gemm_mma<1>, cudaFuncAttributeMaxDynamicSharedMemorySize, SMB);
    cudaFuncSetAttribute(gemm_mma<6>, cudaFuncAttributeMaxDynamicSharedMemorySize, SMB);
    cudaFuncSetAttribute(gemm_mma<5>, cudaFuncAttributeMaxDynamicSharedMemorySize, SMO);

    // launch index (ncu captures index 3 = GEMM-A):
    prep_kernel<<<705, 256>>>(x, ln_g, ln_b, W_in, W_out, W_xproj, W_dt);  // 0
    gemm_mma<1><<<dim3(8, 64), 256, SMB>>>(                                // 1  G1
        p_xnh, p_WinT, nullptr, nullptr, CDIM);
    conv_silu_kernel<<<NROWS, 256>>>(conv_w, conv_b);                      // 2
    gemm_mma<6><<<dim3(1, 64), 256, SMB>>>(                                // 3  GEMM-A
        p_u2h, p_w3T, nullptr, nullptr, DINNER);
    dtbc_kernel<<<NROWS/32, 256>>>(b_dt);                                  // 4
    scan_kernel<<<256, 256>>>(A_log, D_skip);                              // 5
    gemm_mma<5><<<dim3(2, 64), 256, SMO>>>(                                // 6  G4+out
        p_ygh, p_WoutT, out, x, DINNER);
}